// round 7
// baseline (speedup 1.0000x reference)
#include <cuda_runtime.h>
#include <cuda_bf16.h>
#include <cstdint>

// NoiseFilter, exact closed form (validated R3-R5, rel_err 3.4e-7):
//   taps: ir0[j] = (1/128)(amp0 + 2*sum_{k=1..63} amp_k cos(pi*k*j/64) + amp64*(-1)^j)
//         h[j]   = ir0[j] * 0.5*(1+cos(pi*j/64)),  j = 0..63
//   s[t] = 2*u[t]-1,  Z[0..255]=0, Z[256+t]=s[t]
//   out[tau] = sum_{d=0}^{63} h[d] * ( Z[256+tau-d] + Z[tau+d] )
// Wrap-tail (2nd term) only for output groups t0>=192 (q>=48): warps 6-7.
// Phase B uses a packed double-step Chebyshev recurrence (no cos table, 1 MUFU).
// Phase C uses f32x2 FMA with a DUPLICATED tap table so (h,h) pairs are
// adjacent-register (MOV-free) LDS.128 results.

#define PAIRS   4
#define THREADS 256
#define ZSTRIDE 520            // 512 + 8 pad (16B row alignment)
#define PI64    0.04908738521234052f   // pi/64

#define PACK2(dst, lo, hi) \
    asm("mov.b64 %0, {%1, %2};" : "=l"(dst) \
        : "r"(__float_as_uint(lo)), "r"(__float_as_uint(hi)))
#define FMA2(acc, a, b) \
    asm("fma.rn.f32x2 %0, %1, %2, %0;" : "+l"(acc) : "l"(a), "l"(b))
#define FMA2D(dst, a, b, c) \
    asm("fma.rn.f32x2 %0, %1, %2, %3;" : "=l"(dst) : "l"(a), "l"(b), "l"(c))
#define ADD2(dst, a, b) \
    asm("add.rn.f32x2 %0, %1, %2;" : "=l"(dst) : "l"(a), "l"(b))
#define XOR64(dst, a, m) \
    asm("xor.b64 %0, %1, %2;" : "=l"(dst) : "l"(a), "l"(m))
#define UNPACK2(lo, hi, v) \
    asm("mov.b64 {%0, %1}, %2;" : "=r"(lo), "=r"(hi) : "l"(v))

__global__ __launch_bounds__(THREADS)
void noisefilter_kernel(const float* __restrict__ amp,    // [65536, 65]
                        const float* __restrict__ noise,  // [65536, 256]
                        float*       __restrict__ out)    // [65536, 256]
{
    __shared__ __align__(16) float Z[PAIRS][ZSTRIDE];   // zero-padded signal
    __shared__ __align__(16) float hd_sh[PAIRS][136];   // DUPLICATED taps hd[2j]=hd[2j+1]=h[j]
    __shared__ __align__(16) float a_sh[PAIRS][68];     // shifted coeffs (see load loop)

    const int tid = threadIdx.x;

    // tid -> (p, q): q<48 (tail-free) fills warps 0..5; q>=48 warps 6..7.
    int p, q;
    if (tid < 192) { p = tid / 48;      q = tid % 48; }
    else           { int r = tid - 192; p = r >> 4;   q = 48 + (r & 15); }

    const long long pairBase = (long long)blockIdx.x * PAIRS;

    // ---- issue global noise load early ----
    const float4* n4 = (const float4*)noise;
    float4 v = n4[(pairBase + p) * 64 + q];

    // ---- phase A: zero Z, load coeffs ----
    // a_sh layout (per pair): a_sh[i] = 2*amp[i+1] for i=0..62 (so LDS.64 pairs
    // starting at even i are aligned), a_sh[63] = amp[64] (undoubled, pairs with
    // index 62 to fold the Nyquist term), a_sh[64] = amp[0] (DC).
    {
        float4* Zf4 = (float4*)Z;
        #pragma unroll
        for (int i = tid; i < PAIRS * (ZSTRIDE / 4); i += THREADS)
            Zf4[i] = make_float4(0.f, 0.f, 0.f, 0.f);
    }
    for (int i = tid; i < PAIRS * 65; i += THREADS) {
        int pp = i / 65, k = i - pp * 65;
        float vv = amp[(pairBase + pp) * 65 + k];
        int dst; float sc;
        if      (k == 0)  { dst = 64;    sc = 1.f; }
        else if (k == 64) { dst = 63;    sc = 1.f; }
        else              { dst = k - 1; sc = 2.f; }
        a_sh[pp][dst] = sc * vv;
    }
    __syncthreads();

    // ---- phase B: deposit s = 2u-1; taps via packed Chebyshev recurrence ----
    {
        float4 s4 = make_float4(2.f * v.x - 1.f, 2.f * v.y - 1.f,
                                2.f * v.z - 1.f, 2.f * v.w - 1.f);
        ((float4*)(Z[p]))[64 + q] = s4;                  // Z[256+4q .. +3]
    }
    {
        const int j = q;
        const float* a = a_sh[p];
        const float c1 = __cosf((float)j * PI64);        // cos(theta), theta = pi*j/64
        const float c2 = fmaf(2.f * c1, c1, -1.f);       // cos(2 theta)
        const float t2 = 2.f * c2;
        const uint64_t SGN = 0x8000000080000000ull;

        uint64_t P, Pm, T2, ACC;
        PACK2(P,  c1,  c2);                              // (cos k.th, cos (k+1).th), k=1
        PACK2(Pm, -c1, -1.f);                            // -(cos (k-2).th, cos (k-1).th)
        PACK2(T2, t2,  t2);
        PACK2(ACC, a[64], 0.f);                          // DC term amp[0]

        const uint64_t* ap = (const uint64_t*)a;         // aligned coeff pairs
        #pragma unroll
        for (int i = 0; i < 32; i++) {
            FMA2(ACC, ap[i], P);                         // += (a_k, a_{k+1}) .* (c_k, c_{k+1})
            uint64_t Pn;
            FMA2D(Pn, T2, P, Pm);                        // P_{k+2} = t2*P_k - P_{k-2}
            XOR64(Pm, P, SGN);                           // next Pm = -P_k
            P = Pn;
        }
        uint32_t ulo, uhi;
        UNPACK2(ulo, uhi, ACC);
        float acc = __uint_as_float(ulo) + __uint_as_float(uhi);
        float h = acc * (1.f + c1) * (1.f / 256.f);
        hd_sh[p][2 * j]     = h;                         // duplicated store
        hd_sh[p][2 * j + 1] = h;
    }
    __syncthreads();

    // ---- phase C: convolution, 4 outputs/thread, packed FFMA2 ----
    {
        const float4* Z4 = (const float4*)(Z[p]);
        const float4* H8 = (const float4*)(hd_sh[p]);    // H8[2dq]=(h0,h0,h1,h1) ...
        const int base = 64 + q;                         // float4 idx of Z[256+t0]

        uint64_t o01 = 0ull, o23 = 0ull;
        float4 B = Z4[base];                             // causal window hi

        if (q < 48) {
            #pragma unroll
            for (int dq = 0; dq < 16; dq++) {
                const float4 hA = H8[2 * dq];            // (h0,h0,h1,h1)
                const float4 hB = H8[2 * dq + 1];        // (h2,h2,h3,h3)
                const float4 A  = Z4[base - dq - 1];
                uint64_t H00, H11, H22, H33;
                PACK2(H00, hA.x, hA.y); PACK2(H11, hA.z, hA.w);   // adjacent regs: free
                PACK2(H22, hB.x, hB.y); PACK2(H33, hB.z, hB.w);
                uint64_t Pb01, Pb23, Pa23, Pa12, Pa3b0, Pb12;
                PACK2(Pb01, B.x, B.y);  PACK2(Pb23, B.z, B.w);    // free (aligned)
                PACK2(Pa23, A.z, A.w);                            // free
                PACK2(Pa12, A.y, A.z);  PACK2(Pa3b0, A.w, B.x);   // real MOVs
                PACK2(Pb12, B.y, B.z);
                FMA2(o01, H00, Pb01);  FMA2(o23, H00, Pb23);   // d=4dq
                FMA2(o01, H11, Pa3b0); FMA2(o23, H11, Pb12);   // d=4dq+1
                FMA2(o01, H22, Pa23);  FMA2(o23, H22, Pb01);   // d=4dq+2
                FMA2(o01, H33, Pa12);  FMA2(o23, H33, Pa3b0);  // d=4dq+3
                B = A;
            }
        } else {
            float4 C = Z4[q];                            // tail window lo
            #pragma unroll
            for (int dq = 0; dq < 16; dq++) {
                const float4 hA = H8[2 * dq];
                const float4 hB = H8[2 * dq + 1];
                const float4 A  = Z4[base - dq - 1];
                const float4 D  = Z4[q + dq + 1];
                uint64_t H00, H11, H22, H33;
                PACK2(H00, hA.x, hA.y); PACK2(H11, hA.z, hA.w);
                PACK2(H22, hB.x, hB.y); PACK2(H33, hB.z, hB.w);
                uint64_t Pb01, Pb23, Pa23, Pa12, Pa3b0, Pb12;
                PACK2(Pb01, B.x, B.y);  PACK2(Pb23, B.z, B.w);
                PACK2(Pa23, A.z, A.w);  PACK2(Pa12, A.y, A.z);
                PACK2(Pa3b0, A.w, B.x); PACK2(Pb12, B.y, B.z);
                uint64_t Pc01, Pc23, Pc12, Pc3d0, Pd01, Pd12;
                PACK2(Pc01, C.x, C.y);  PACK2(Pc23, C.z, C.w);
                PACK2(Pc12, C.y, C.z);  PACK2(Pc3d0, C.w, D.x);
                PACK2(Pd01, D.x, D.y);  PACK2(Pd12, D.y, D.z);
                uint64_t S0, S1;
                ADD2(S0, Pb01, Pc01);  ADD2(S1, Pb23, Pc23);   // d=4dq
                FMA2(o01, H00, S0);    FMA2(o23, H00, S1);
                ADD2(S0, Pa3b0, Pc12); ADD2(S1, Pb12, Pc3d0);  // d=4dq+1
                FMA2(o01, H11, S0);    FMA2(o23, H11, S1);
                ADD2(S0, Pa23, Pc23);  ADD2(S1, Pb01, Pd01);   // d=4dq+2
                FMA2(o01, H22, S0);    FMA2(o23, H22, S1);
                ADD2(S0, Pa12, Pc3d0); ADD2(S1, Pa3b0, Pd12);  // d=4dq+3
                FMA2(o01, H33, S0);    FMA2(o23, H33, S1);
                B = A;
                C = D;
            }
        }

        uint32_t u0, u1, u2, u3;
        UNPACK2(u0, u1, o01);
        UNPACK2(u2, u3, o23);
        ((float4*)out)[(pairBase + p) * 64 + q] =
            make_float4(__uint_as_float(u0), __uint_as_float(u1),
                        __uint_as_float(u2), __uint_as_float(u3));
    }
}

extern "C" void kernel_launch(void* const* d_in, const int* in_sizes, int n_in,
                              void* d_out, int out_size)
{
    const float* amp   = (const float*)d_in[0];   // filter_bank [16,4096,65]
    const float* noise = (const float*)d_in[1];   // noise_u     [16,4096,256]
    float* out = (float*)d_out;                   // [16, 4096*256, 1]

    const int total_pairs = in_sizes[0] / 65;     // 65536
    const int blocks = total_pairs / PAIRS;       // 16384
    noisefilter_kernel<<<blocks, THREADS>>>(amp, noise, out);
}

// round 8
// speedup vs baseline: 1.5277x; 1.5277x over previous
#include <cuda_runtime.h>
#include <cuda_bf16.h>
#include <cstdint>

// NoiseFilter, exact closed form (validated R3-R6, rel_err ~3e-7):
//   taps: ir0[j] = (1/128)(amp0 + 2*sum_{k=1..63} amp_k cos(pi*k*j/64) + amp64*(-1)^j)
//         h[j]   = ir0[j] * 0.5*(1+cos(pi*j/64)),  j = 0..63
//   s[t] = 2*u[t]-1,  Z[0..255]=0, Z[256+t]=s[t]
//   out[tau] = sum_{d=0}^{63} h[d] * ( Z[256+tau-d] + Z[tau+d] )
// Wrap-tail (2nd term) only for output groups t0>=192 (q>=48): warps 6-7.
// Phase B: symmetric pairs — ir0(64-j) = E(j)-O(j) with E/O = even/odd-k sums
// of ir0(j)=E+O; 33 workers/pair compute all 64 taps (MUFU work ~0.6x).
// Taps stored as duplicated uint64 (h,h): conv reads LDS.64 broadcast directly
// into FMA2 operand pairs — zero tap MOVs.

#define PAIRS   4
#define THREADS 256
#define ZSTRIDE 520            // 512 + 8 pad (16B row alignment)
#define PI64    0.04908738521234052f   // pi/64

#define PACK2(dst, lo, hi) \
    asm("mov.b64 %0, {%1, %2};" : "=l"(dst) \
        : "r"(__float_as_uint(lo)), "r"(__float_as_uint(hi)))
#define FMA2(acc, a, b) \
    asm("fma.rn.f32x2 %0, %1, %2, %0;" : "+l"(acc) : "l"(a), "l"(b))
#define ADD2(dst, a, b) \
    asm("add.rn.f32x2 %0, %1, %2;" : "=l"(dst) : "l"(a), "l"(b))
#define UNPACK2(lo, hi, v) \
    asm("mov.b64 {%0, %1}, %2;" : "=r"(lo), "=r"(hi) : "l"(v))

__global__ __launch_bounds__(THREADS)
void noisefilter_kernel(const float* __restrict__ amp,    // [65536, 65]
                        const float* __restrict__ noise,  // [65536, 256]
                        float*       __restrict__ out)    // [65536, 256]
{
    __shared__ __align__(16) float    Z[PAIRS][ZSTRIDE];  // zero-padded signal
    __shared__ __align__(16) uint64_t hd64[PAIRS][64];    // duplicated taps (h_d, h_d)
    __shared__ __align__(16) float    a_sh[PAIRS][68];    // 2*amp

    const int tid = threadIdx.x;

    // tid -> (p, q): q<48 (tail-free) fills warps 0..5; q>=48 warps 6..7.
    int p, q;
    if (tid < 192) { p = tid / 48;      q = tid % 48; }
    else           { int r = tid - 192; p = r >> 4;   q = 48 + (r & 15); }

    const long long pairBase = (long long)blockIdx.x * PAIRS;

    // ---- issue global noise load early ----
    const float4* n4 = (const float4*)noise;
    float4 v = n4[(pairBase + p) * 64 + q];

    // ---- phase A: zero Z, load amp (doubled) ----
    {
        float4* Zf4 = (float4*)Z;
        #pragma unroll
        for (int i = tid; i < PAIRS * (ZSTRIDE / 4); i += THREADS)
            Zf4[i] = make_float4(0.f, 0.f, 0.f, 0.f);
    }
    for (int i = tid; i < PAIRS * 65; i += THREADS) {
        int pp = i / 65, k = i - pp * 65;
        a_sh[pp][k] = 2.f * amp[(pairBase + pp) * 65 + k];
    }
    __syncthreads();

    // ---- phase B: deposit s = 2u-1; taps via symmetric-pair DCT ----
    {
        float4 s4 = make_float4(2.f * v.x - 1.f, 2.f * v.y - 1.f,
                                2.f * v.z - 1.f, 2.f * v.w - 1.f);
        ((float4*)(Z[p]))[64 + q] = s4;                  // Z[256+4q .. +3]
    }
    if (tid < 132) {                                     // warps 0..3 + 4 lanes of warp 4
        const int pp = tid & 3;
        const int jj = tid >> 2;                         // 0..32
        const float* a = a_sh[pp];
        // E = even-k sum (incl DC, Nyquist), O = odd-k sum; a[] holds 2*amp.
        float e = 0.5f * a[0] + ((jj & 1) ? -0.5f : 0.5f) * a[64];
        float o = 0.f;
        int m = 0;
        #pragma unroll
        for (int k = 1; k < 64; k++) {
            m = (m + jj) & 127;                          // (k*jj) mod 128
            float c = __cosf((float)m * PI64);
            if (k & 1) o = fmaf(a[k], c, o);
            else       e = fmaf(a[k], c, e);
        }
        float c1 = __cosf((float)jj * PI64);             // cos(pi*jj/64)
        float hj = (e + o) * (1.f + c1) * (1.f / 256.f); // tap jj
        uint64_t d0; PACK2(d0, hj, hj);
        hd64[pp][jj] = d0;
        if (jj >= 1) {                                   // partner tap 64-jj
            float hp = (e - o) * (1.f - c1) * (1.f / 256.f);
            uint64_t d1; PACK2(d1, hp, hp);
            hd64[pp][64 - jj] = d1;                      // jj=32 rewrites same slot
        }
    }
    __syncthreads();

    // ---- phase C: convolution, 4 outputs/thread, packed FFMA2 ----
    {
        const float4*   Z4 = (const float4*)(Z[p]);
        const uint64_t* Hd = hd64[p];
        const int base = 64 + q;                         // float4 idx of Z[256+t0]

        uint64_t o01 = 0ull, o23 = 0ull;
        float4 B = Z4[base];                             // causal window hi

        if (q < 48) {
            #pragma unroll
            for (int dq = 0; dq < 16; dq++) {
                const uint64_t H00 = Hd[4 * dq + 0];     // (h,h): direct FMA2 operand
                const uint64_t H11 = Hd[4 * dq + 1];
                const uint64_t H22 = Hd[4 * dq + 2];
                const uint64_t H33 = Hd[4 * dq + 3];
                const float4 A = Z4[base - dq - 1];
                uint64_t Pb01, Pb23, Pa23, Pa12, Pa3b0, Pb12;
                PACK2(Pb01, B.x, B.y);  PACK2(Pb23, B.z, B.w);   // aligned: elided
                PACK2(Pa23, A.z, A.w);
                PACK2(Pa12, A.y, A.z);  PACK2(Pa3b0, A.w, B.x);  // real MOVs
                PACK2(Pb12, B.y, B.z);
                FMA2(o01, H00, Pb01);  FMA2(o23, H00, Pb23);   // d=4dq
                FMA2(o01, H11, Pa3b0); FMA2(o23, H11, Pb12);   // d=4dq+1
                FMA2(o01, H22, Pa23);  FMA2(o23, H22, Pb01);   // d=4dq+2
                FMA2(o01, H33, Pa12);  FMA2(o23, H33, Pa3b0);  // d=4dq+3
                B = A;
            }
        } else {
            float4 C = Z4[q];                            // tail window lo
            #pragma unroll
            for (int dq = 0; dq < 16; dq++) {
                const uint64_t H00 = Hd[4 * dq + 0];
                const uint64_t H11 = Hd[4 * dq + 1];
                const uint64_t H22 = Hd[4 * dq + 2];
                const uint64_t H33 = Hd[4 * dq + 3];
                const float4 A = Z4[base - dq - 1];
                const float4 D = Z4[q + dq + 1];
                uint64_t Pb01, Pb23, Pa23, Pa12, Pa3b0, Pb12;
                PACK2(Pb01, B.x, B.y);  PACK2(Pb23, B.z, B.w);
                PACK2(Pa23, A.z, A.w);  PACK2(Pa12, A.y, A.z);
                PACK2(Pa3b0, A.w, B.x); PACK2(Pb12, B.y, B.z);
                uint64_t Pc01, Pc23, Pc12, Pc3d0, Pd01, Pd12;
                PACK2(Pc01, C.x, C.y);  PACK2(Pc23, C.z, C.w);
                PACK2(Pc12, C.y, C.z);  PACK2(Pc3d0, C.w, D.x);
                PACK2(Pd01, D.x, D.y);  PACK2(Pd12, D.y, D.z);
                uint64_t S0, S1;
                ADD2(S0, Pb01, Pc01);  ADD2(S1, Pb23, Pc23);   // d=4dq
                FMA2(o01, H00, S0);    FMA2(o23, H00, S1);
                ADD2(S0, Pa3b0, Pc12); ADD2(S1, Pb12, Pc3d0);  // d=4dq+1
                FMA2(o01, H11, S0);    FMA2(o23, H11, S1);
                ADD2(S0, Pa23, Pc23);  ADD2(S1, Pb01, Pd01);   // d=4dq+2
                FMA2(o01, H22, S0);    FMA2(o23, H22, S1);
                ADD2(S0, Pa12, Pc3d0); ADD2(S1, Pa3b0, Pd12);  // d=4dq+3
                FMA2(o01, H33, S0);    FMA2(o23, H33, S1);
                B = A;
                C = D;
            }
        }

        uint32_t u0, u1, u2, u3;
        UNPACK2(u0, u1, o01);
        UNPACK2(u2, u3, o23);
        ((float4*)out)[(pairBase + p) * 64 + q] =
            make_float4(__uint_as_float(u0), __uint_as_float(u1),
                        __uint_as_float(u2), __uint_as_float(u3));
    }
}

extern "C" void kernel_launch(void* const* d_in, const int* in_sizes, int n_in,
                              void* d_out, int out_size)
{
    const float* amp   = (const float*)d_in[0];   // filter_bank [16,4096,65]
    const float* noise = (const float*)d_in[1];   // noise_u     [16,4096,256]
    float* out = (float*)d_out;                   // [16, 4096*256, 1]

    const int total_pairs = in_sizes[0] / 65;     // 65536
    const int blocks = total_pairs / PAIRS;       // 16384
    noisefilter_kernel<<<blocks, THREADS>>>(amp, noise, out);
}